// round 14
// baseline (speedup 1.0000x reference)
#include <cuda_runtime.h>
#include <cuda_fp16.h>
#include <stdint.h>
#include <math.h>

// BlockCirculant via FFT:  out = ifft( fft(x*d blocks) * conj(fft(W)) ) + bias
// 6 independent 128-thread row pipelines per CTA (named barriers, 24 warps),
// in-place FFT-256 (16x16 Cooley-Tukey), fp16 intermediate buffers,
// low-register einsum (on-the-fly f32x2 packing), L2 prefetch for next row.

#define K16   16
#define BSZ   256
#define NF    129        // Hermitian frequencies 0..128
#define DIN   4096
#define NB    8192
#define GP    272        // half2 per FFT group scratch (16*17)
#define NSLOT 6
#define TPB   768

// Wf[f*256 + ((ij + 4f) & 255)] = conj(FFT(W[i,j,:]))[f] / 256   (half2)
__device__ __half2 g_Wf[NF * 256];

__device__ __forceinline__ void cmul(float& xr, float& xi, float wr, float wi) {
    float tr = xr * wr - xi * wi;
    xi       = xr * wi + xi * wr;
    xr       = tr;
}

// ---- packed fp32x2 helpers (Blackwell FFMA2) ----
__device__ __forceinline__ unsigned long long pk2(float lo, float hi) {
    unsigned long long r;
    asm("mov.b64 %0, {%1, %2};" : "=l"(r) : "f"(lo), "f"(hi));
    return r;
}
__device__ __forceinline__ float2 upk2(unsigned long long v) {
    float2 r;
    asm("mov.b64 {%0, %1}, %2;" : "=f"(r.x), "=f"(r.y) : "l"(v));
    return r;
}
__device__ __forceinline__ unsigned long long ffma2(unsigned long long a,
                                                    unsigned long long b,
                                                    unsigned long long c) {
    unsigned long long d;
    asm("fma.rn.f32x2 %0, %1, %2, %3;" : "=l"(d) : "l"(a), "l"(b), "l"(c));
    return d;
}
__device__ __forceinline__ void prefetchL2(const void* p) {
    asm volatile("prefetch.global.L2 [%0];" :: "l"(p));
}

template <bool INV>
__device__ __forceinline__ void fft16(float* re, float* im) {
    {
        float tr, ti;
#define SWP(a, b) tr = re[a]; re[a] = re[b]; re[b] = tr; \
                  ti = im[a]; im[a] = im[b]; im[b] = ti;
        SWP(1, 8) SWP(2, 4) SWP(3, 12) SWP(5, 10) SWP(7, 14) SWP(11, 13)
#undef SWP
    }
    constexpr float C1 = 0.923879532511286756f;
    constexpr float S1 = 0.382683432365089772f;
    constexpr float R  = 0.707106781186547524f;
    const float C16[8] = {1.f,  C1,  R,  S1, 0.f, -S1, -R, -C1};
    const float S16[8] = {0.f,  S1,  R,  C1, 1.f,  C1,  R,  S1};
#pragma unroll
    for (int s = 0; s < 4; ++s) {
        const int h = 1 << s;
#pragma unroll
        for (int g = 0; g < 16; g += (h << 1)) {
#pragma unroll
            for (int j = 0; j < h; ++j) {
                const int m = j << (3 - s);
                const float wr = C16[m];
                const float wi = INV ? S16[m] : -S16[m];
                const int a = g + j, b = a + h;
                float tr = re[b] * wr - im[b] * wi;
                float ti = re[b] * wi + im[b] * wr;
                re[b] = re[a] - tr; im[b] = im[a] - ti;
                re[a] += tr;        im[a] += ti;
            }
        }
    }
}

// ---------------- W_fft precompute (per launch, cheap) ----------------
__global__ void bc_wfft(const float* __restrict__ W) {
    __shared__ float2 tw[256];
    __shared__ float  wv[256];
    const int ij  = blockIdx.x;      // i*16 + j
    const int tid = threadIdx.x;
    float sv, cv;
    float ang = 6.2831853071795864769f * (float)tid * (1.0f / 256.0f);  // +sign: conj folded
    sincosf(ang, &sv, &cv);
    tw[tid] = make_float2(cv, sv);
    wv[tid] = W[ij * BSZ + tid];
    __syncthreads();
    if (tid < NF) {
        float ar = 0.f, ai = 0.f;
        for (int n = 0; n < 256; ++n) {
            float2 e = tw[(tid * n) & 255];
            ar += wv[n] * e.x;
            ai += wv[n] * e.y;
        }
        // rotated layout: position (ij + 4f) & 255 within row f
        g_Wf[tid * 256 + ((ij + 4 * tid) & 255)] =
            __floats2half2_rn(ar * (1.f / 256.f), ai * (1.f / 256.f));
    }
}

// ---------------- main fused kernel ----------------
__global__ void __launch_bounds__(TPB, 1)
bc_main(const float* __restrict__ x, const float* __restrict__ d,
        const float* __restrict__ bias, float* __restrict__ out) {
    extern __shared__ char smem_raw[];
    __half2* Wcs = (__half2*)smem_raw;                          // 132096 B  (129*256 half2)
    float2*  twf = (float2*)(smem_raw + 132096);                //   2048 B
    float*   ds  = (float*) (smem_raw + 132096 + 2048);         //  16384 B
    __half2* bufs = (__half2*)(smem_raw + 150528);              //  52224 B (6 slots x 8 groups x 272)

    const int tid = threadIdx.x;
    {
        const unsigned int* src = (const unsigned int*)g_Wf;
        unsigned int* dst = (unsigned int*)Wcs;
        for (int i2 = tid; i2 < NF * 256; i2 += TPB) dst[i2] = src[i2];
        if (tid < 256) {
            float sv, cv;
            float ang = -6.2831853071795864769f * (float)tid * (1.0f / 256.0f);
            sincosf(ang, &sv, &cv);
            twf[tid] = make_float2(cv, sv);   // e^{-2pi i m /256}
        }
        for (int i2 = tid; i2 < DIN; i2 += TPB) ds[i2] = d[i2];
    }
    __syncthreads();

    const int slot = tid >> 7;        // 0..5: independent row pipeline
    const int t128 = tid & 127;
    const int g    = t128 >> 4;       // FFT group 0..7 (pair of blocks)
    const int t    = t128 & 15;       // lane within FFT
    const int barid = slot + 1;
    __half2* Zb = bufs + slot * (8 * GP);
    __half2* gb = Zb + g * GP;
    const float4* ds4 = (const float4*)ds;

    float re[16], im[16];

#define BARS() asm volatile("bar.sync %0, 128;" :: "r"(barid) : "memory")

    const int rstride = gridDim.x * NSLOT;
    int row0 = blockIdx.x * NSLOT + slot;
    // prime L2 with first row
    if (row0 < NB) {
        const char* p = (const char*)(x + (size_t)row0 * DIN) + t128 * 32;
        prefetchL2(p);
    }

    for (int row = row0; row < NB; row += rstride) {
        // ---- P0: load row (float4, L2-warm), multiply by d, scatter to tiles ----
        {
            const float4* xr4 = (const float4*)(x + (size_t)row * DIN);
#pragma unroll
            for (int it = 0; it < 8; ++it) {
                int c4 = t128 + (it << 7);
                float4 xv = xr4[c4];
                float4 dv = ds4[c4];
                float v[4] = {xv.x * dv.x, xv.y * dv.y, xv.z * dv.z, xv.w * dv.w};
#pragma unroll
                for (int e = 0; e < 4; ++e) {
                    int col = (c4 << 2) + e;
                    int p = col >> 9;          // group (2 blocks of 256)
                    int n = col & 255;
                    __half* dstp = (__half*)(Zb + p * GP + (n & 15) * 17 + (n >> 4));
                    dstp[(col >> 8) & 1] = __float2half(v[e]);
                }
            }
        }
        BARS();

        // ---- prefetch next row into L2 (no registers held) ----
        {
            int nrow = row + rstride;
            if (nrow < NB) {
                const char* p = (const char*)(x + (size_t)nrow * DIN) + t128 * 128;
                prefetchL2(p);   // 128 threads x 128B = full 16KB row
            }
        }

        // ---- forward FFT-256, in place within each group tile ----
#pragma unroll
        for (int n1 = 0; n1 < 16; ++n1) {
            float2 v = __half22float2(gb[t * 17 + n1]);
            re[n1] = v.x; im[n1] = v.y;
        }
        fft16<false>(re, im);
        __syncwarp();
#pragma unroll
        for (int k1 = 0; k1 < 16; ++k1) {
            if (k1 > 0) {
                float2 w = twf[(t * k1) & 255];
                cmul(re[k1], im[k1], w.x, w.y);
            }
            gb[k1 * 17 + t] = __floats2half2_rn(re[k1], im[k1]);
        }
        __syncwarp();
#pragma unroll
        for (int n2 = 0; n2 < 16; ++n2) {
            float2 v = __half22float2(gb[t * 17 + n2]);
            re[n2] = v.x; im[n2] = v.y;
        }
        fft16<false>(re, im);
        __syncwarp();
#pragma unroll
        for (int k2 = 0; k2 < 16; ++k2)
            gb[(k2 << 4) + t] = __floats2half2_rn(re[k2], im[k2]);
        BARS();

        // ---- einsum (in place, fused Hermitian unpack + repack) ----
        {
            const int f  = t128;            // 0..127
            const int mf = (256 - f) & 255;
            // reuse re[]/im[] as xr[]/xi[] to keep register pressure low
            float* xr = re;
            float* xi = im;
#pragma unroll
            for (int p = 0; p < 8; ++p) {
                float2 a = __half22float2(Zb[p * GP + f]);
                float2 b = __half22float2(Zb[p * GP + mf]);
                xr[2 * p]     = 0.5f * (a.x + b.x);
                xi[2 * p]     = 0.5f * (a.y - b.y);
                xr[2 * p + 1] = 0.5f * (a.y + b.y);
                xi[2 * p + 1] = 0.5f * (b.x - a.x);
            }
            const uint4* W4 = ((const uint4*)Wcs) + f * 64;   // row f: 256 half2 = 64 uint4
#pragma unroll
            for (int gg = 0; gg < 8; ++gg) {
                unsigned long long A1 = 0ull, A2 = 0ull, B1 = 0ull, B2 = 0ull;
                const int ia = 2 * gg, ib = 2 * gg + 1;
#pragma unroll
                for (int jc = 0; jc < 4; ++jc) {
                    uint4 wa = W4[(ia * 4 + jc + f) & 63];
                    uint4 wb = W4[(ib * 4 + jc + f) & 63];
                    unsigned int wax[4] = {wa.x, wa.y, wa.z, wa.w};
                    unsigned int wbx[4] = {wb.x, wb.y, wb.z, wb.w};
#pragma unroll
                    for (int e = 0; e < 4; ++e) {
                        const int j = jc * 4 + e;
                        unsigned long long xrr = pk2(xr[j], xr[j]);
                        unsigned long long xii = pk2(xi[j], xi[j]);
                        float2 w1 = __half22float2(*(__half2*)&wax[e]);
                        unsigned long long wd1 = pk2(w1.x, w1.y);
                        A1 = ffma2(xrr, wd1, A1);
                        A2 = ffma2(xii, wd1, A2);
                        float2 w2 = __half22float2(*(__half2*)&wbx[e]);
                        unsigned long long wd2 = pk2(w2.x, w2.y);
                        B1 = ffma2(xrr, wd2, B1);
                        B2 = ffma2(xii, wd2, B2);
                    }
                }
                float2 a1 = upk2(A1), a2 = upk2(A2);
                float2 b1 = upk2(B1), b2 = upk2(B2);
                float ar = a1.x - a2.y, ai = a1.y + a2.x;   // Y_{2gg}[f]
                float br = b1.x - b2.y, bi = b1.y + b2.x;   // Y_{2gg+1}[f]
                Zb[gg * GP + f] = __floats2half2_rn(ar - bi, ai + br);
                if (f > 0)
                    Zb[gg * GP + 256 - f] = __floats2half2_rn(ar + bi, br - ai);
            }
            // Nyquist f=128: real spectra, 16 threads do 16 real dot products
            if (t128 < 16) {
                float xn[16];
#pragma unroll
                for (int p = 0; p < 8; ++p) {
                    float2 z = __half22float2(Zb[p * GP + 128]);
                    xn[2 * p] = z.x; xn[2 * p + 1] = z.y;
                }
                float acc = 0.f;
#pragma unroll
                for (int j = 0; j < 16; ++j)
                    acc += xn[j] * __low2float(Wcs[128 * 256 + t128 * 16 + j]);
                __syncwarp(0x0000FFFFu);
                ((__half*)(Zb + (t128 >> 1) * GP + 128))[t128 & 1] = __float2half(acc);
            }
        }
        BARS();

        // ---- inverse FFT-256, in place; add bias; store ----
#pragma unroll
        for (int n1 = 0; n1 < 16; ++n1) {
            float2 v = __half22float2(gb[(n1 << 4) + t]);
            re[n1] = v.x; im[n1] = v.y;
        }
        fft16<true>(re, im);
        __syncwarp();
#pragma unroll
        for (int k1 = 0; k1 < 16; ++k1) {
            if (k1 > 0) {
                float2 w = twf[(t * k1) & 255];
                cmul(re[k1], im[k1], w.x, -w.y);   // conj twiddle
            }
            gb[k1 * 17 + t] = __floats2half2_rn(re[k1], im[k1]);
        }
        __syncwarp();
#pragma unroll
        for (int n2 = 0; n2 < 16; ++n2) {
            float2 v = __half22float2(gb[t * 17 + n2]);
            re[n2] = v.x; im[n2] = v.y;
        }
        fft16<true>(re, im);
        {
            float* orow = out + (size_t)row * DIN + (g << 9);
            const float* brow = bias + (g << 9);
#pragma unroll
            for (int k2 = 0; k2 < 16; ++k2) {
                int n = (k2 << 4) + t;
                orow[n]       = re[k2] + __ldg(brow + n);        // even block (real)
                orow[n + 256] = im[k2] + __ldg(brow + n + 256);  // odd block (imag)
            }
        }
        BARS();   // protect buffer before next iteration's P0
    }
#undef BARS
}

extern "C" void kernel_launch(void* const* d_in, const int* in_sizes, int n_in,
                              void* d_out, int out_size) {
    const float* x    = (const float*)d_in[0];
    const float* W    = (const float*)d_in[1];
    const float* d    = (const float*)d_in[2];
    const float* bias = (const float*)d_in[3];
    float* out = (float*)d_out;

    const size_t SMEM = 132096 + 2048 + 16384 + (size_t)NSLOT * 8 * GP * sizeof(__half2); // 202752
    cudaFuncSetAttribute(bc_main, cudaFuncAttributeMaxDynamicSharedMemorySize, (int)SMEM);

    bc_wfft<<<K16 * K16, 256>>>(W);
    bc_main<<<152, TPB, SMEM>>>(x, d, bias, out);
    (void)in_sizes; (void)n_in; (void)out_size;
}